// round 7
// baseline (speedup 1.0000x reference)
#include <cuda_runtime.h>
#include <cstdint>

// Problem constants
#define NB 2048
#define NT 64
#define NC 384
#define NH 12
#define ND 32
#define N3C 1152
#define MT 131072            // NB*NT rows
#define KDIM 384
#define SQ 50331648ull       // NB*NH*NT*ND

// ---------------- device scratch (no allocation allowed) -------------------
__device__ float g_qkv_hi[3 * SQ];                  // tf32-valued hi planes
__device__ float g_qkv_lo[3 * SQ];                  // tf32-valued lo planes
__device__ float g_bias[NH * NT * NT];              // (H,T,T)
__device__ float g_xt[(size_t)MT * NC];             // tf32-rounded x
__device__ float g_qwt[(size_t)N3C * NC];           // tf32-rounded qkv_w
__device__ float g_pwt[(size_t)NC * NC];            // tf32-rounded proj_w
__device__ float g_att[(size_t)MT * NC];            // attn output (tf32-rounded)

// ---------------- helpers ---------------------------------------------------
__device__ __forceinline__ uint32_t smem_u32(const void* p) {
    uint32_t a;
    asm("{ .reg .u64 t; cvta.to.shared.u64 t, %1; cvt.u32.u64 %0, t; }"
        : "=r"(a) : "l"(p));
    return a;
}
__device__ __forceinline__ float tf32r(float x) {
    uint32_t u; asm("cvt.rna.tf32.f32 %0, %1;" : "=r"(u) : "f"(x));
    return __uint_as_float(u);
}

#define CP_ASYNC16(dst, src) \
    asm volatile("cp.async.cg.shared.global [%0], [%1], 16;" \
                 :: "r"(dst), "l"(src) : "memory")
#define CP_COMMIT() asm volatile("cp.async.commit_group;" ::: "memory")
#define CP_WAIT(n)  asm volatile("cp.async.wait_group %0;" :: "n"(n) : "memory")

__device__ __forceinline__ void ldsm4(uint32_t& r0, uint32_t& r1,
                                      uint32_t& r2, uint32_t& r3, uint32_t a) {
    asm volatile("ldmatrix.sync.aligned.m8n8.x4.shared.b16 {%0,%1,%2,%3}, [%4];"
                 : "=r"(r0), "=r"(r1), "=r"(r2), "=r"(r3) : "r"(a));
}

__device__ __forceinline__ void mma_tf32(float c[4],
                                         uint32_t a0, uint32_t a1, uint32_t a2, uint32_t a3,
                                         uint32_t b0, uint32_t b1) {
    asm volatile(
        "mma.sync.aligned.m16n8k8.row.col.f32.tf32.tf32.f32 "
        "{%0,%1,%2,%3},{%4,%5,%6,%7},{%8,%9},{%0,%1,%2,%3};"
        : "+f"(c[0]), "+f"(c[1]), "+f"(c[2]), "+f"(c[3])
        : "r"(a0), "r"(a1), "r"(a2), "r"(a3), "r"(b0), "r"(b1));
}

// ---------------------------------------------------------------------------
// tf32 rounding pass (fp32 -> tf32-rounded fp32)
// ---------------------------------------------------------------------------
__global__ void round_kernel(const float* __restrict__ src,
                             float* __restrict__ dst, int n4) {
    int i = blockIdx.x * 256 + threadIdx.x;
    if (i >= n4) return;
    float4 v = ((const float4*)src)[i];
    v.x = tf32r(v.x); v.y = tf32r(v.y); v.z = tf32r(v.z); v.w = tf32r(v.w);
    ((float4*)dst)[i] = v;
}

// ---------------------------------------------------------------------------
// Bias gather
// ---------------------------------------------------------------------------
__global__ void bias_kernel(const float* __restrict__ rpb,
                            const int* __restrict__ rpi) {
    int i = blockIdx.x * 256 + threadIdx.x;
    if (i >= NH * NT * NT) return;
    int h  = i / (NT * NT);
    int qk = i - h * (NT * NT);
    g_bias[i] = rpb[rpi[qk] * NH + h];
}

// ---------------------------------------------------------------------------
// Single-pass TF32 GEMM: C[m][n] = sum_k A[m][k]*W[n][k] + bias[n]
// BM=256, BN=128, BK=32 fp32 (128B swizzled rows). 8 warps (4x2),
// warp tile 64x64. ldmatrix-b16 trick, cp.async double buffer.
// EPI==0: scatter tf32 hi/lo planes into g_qkv_{hi,lo} with q-scale.
// EPI==1: write out (+bias).
// ---------------------------------------------------------------------------
#define STG 49152               // A 32KB + W 16KB per stage
#define SMT (2 * STG)           // 96 KB

template <int EPI>
__global__ void __launch_bounds__(256, 1)
tf_gemm(const float* __restrict__ A, const float* __restrict__ W,
        const float* __restrict__ bias, float* __restrict__ out) {
    extern __shared__ char smem[];
    const uint32_t sb = smem_u32(smem);

    const int tid  = threadIdx.x;
    const int warp = tid >> 5;
    const int lane = tid & 31;
    const int m0 = blockIdx.y * 256;
    const int n0 = blockIdx.x * 128;

    const int wm = (warp >> 1) * 64;    // 0,64,128,192
    const int wn = (warp & 1) * 64;     // 0,64

    // loaders: A one full 32-fp32 row per thread; W half row per thread
    const float* Ap = A + (size_t)(m0 + tid) * KDIM;
    const float* Wp = W + (size_t)(n0 + (tid >> 1)) * KDIM + (size_t)(tid & 1) * 16;
    const uint32_t arow128 = tid * 128;
    const uint32_t wrow128 = (tid >> 1) * 128;
    const int asw = tid & 7;
    const int wcb = (tid & 1) * 4;
    const int wsw = (tid >> 1) & 7;

    auto fill = [&](int kc, int s) {
        const uint32_t base = sb + s * STG;
#pragma unroll
        for (int c = 0; c < 8; c++) {
            const uint32_t off = arow128 + (((uint32_t)(c ^ asw)) << 4);
            CP_ASYNC16(base + off, Ap + kc * 32 + c * 4);
        }
#pragma unroll
        for (int c = 0; c < 4; c++) {
            const uint32_t off = wrow128 + (((uint32_t)((wcb + c) ^ wsw)) << 4);
            CP_ASYNC16(base + 32768 + off, Wp + kc * 32 + c * 4);
        }
    };

    float acc[4][8][4];
#pragma unroll
    for (int i = 0; i < 4; i++)
#pragma unroll
        for (int j = 0; j < 8; j++)
#pragma unroll
            for (int r = 0; r < 4; r++) acc[i][j][r] = 0.0f;

    const int mat = lane >> 3;      // 0..3
    const int mr  = lane & 7;       // 0..7

    fill(0, 0); CP_COMMIT();

    for (int kc = 0; kc < 12; ++kc) {
        const int s = kc & 1;
        if (kc + 1 < 12) { fill(kc + 1, s ^ 1); CP_COMMIT(); CP_WAIT(1); }
        else             { CP_WAIT(0); }
        __syncthreads();

        const uint32_t smA = sb + s * STG;
        const uint32_t smW = smA + 32768;

#pragma unroll
        for (int kg = 0; kg < 4; kg++) {   // 4 x k8 per BK=32
            // A fragments for 4 m16 tiles
            uint32_t af[4][4];
            const uint32_t achunk = ((uint32_t)(kg * 2 + (mat >> 1)) ^ (uint32_t)mr) << 4;
            const uint32_t arow   = wm + ((mat & 1) << 3) + mr;
#pragma unroll
            for (int tm = 0; tm < 4; tm++) {
                const uint32_t ad = smA + (arow + tm * 16) * 128 + achunk;
                ldsm4(af[tm][0], af[tm][1], af[tm][2], af[tm][3], ad);
            }
            const uint32_t bchunk = ((uint32_t)(kg * 2 + (mat & 1)) ^ (uint32_t)mr) << 4;
            // 8 n8-tiles in 2 groups of 4 (limit register pressure)
#pragma unroll
            for (int g2 = 0; g2 < 2; g2++) {
                uint32_t bf[4][2];
#pragma unroll
                for (int p = 0; p < 2; p++) {
                    const uint32_t brow = wn + g2 * 32 + (2 * p + (mat >> 1)) * 8 + mr;
                    const uint32_t bd = smW + brow * 128 + bchunk;
                    uint32_t t0, t1, t2, t3;
                    ldsm4(t0, t1, t2, t3, bd);
                    bf[2 * p][0] = t0; bf[2 * p][1] = t1;
                    bf[2 * p + 1][0] = t2; bf[2 * p + 1][1] = t3;
                }
#pragma unroll
                for (int tm = 0; tm < 4; tm++)
#pragma unroll
                    for (int tn = 0; tn < 4; tn++)
                        mma_tf32(acc[tm][g2 * 4 + tn],
                                 af[tm][0], af[tm][1], af[tm][2], af[tm][3],
                                 bf[tn][0], bf[tn][1]);
            }
        }
        __syncthreads();
    }

    // epilogue
    const int rA = lane >> 2;
    const int cA = lane & 3;
#pragma unroll
    for (int tm = 0; tm < 4; tm++) {
#pragma unroll
        for (int tn = 0; tn < 8; tn++) {
#pragma unroll
            for (int half = 0; half < 2; half++) {
                const int m = m0 + wm + tm * 16 + rA + half * 8;
                const int n = n0 + wn + tn * 8 + cA * 2;
                float v0 = acc[tm][tn][half * 2 + 0] + bias[n];
                float v1 = acc[tm][tn][half * 2 + 1] + bias[n + 1];
                if (EPI == 0) {
                    const int s   = n / NC;
                    const int rem = n - s * NC;
                    const int h   = rem >> 5;
                    const int d0  = rem & 31;
                    if (s == 0) {
                        const float sc = 0.17677669529663687f;  // 1/sqrt(32)
                        v0 *= sc; v1 *= sc;
                    }
                    const int b = m >> 6;
                    const int t = m & 63;
                    const size_t off = (size_t)s * SQ +
                        (((size_t)(b * NH + h)) * NT + t) * ND + d0;
                    float h0 = tf32r(v0), h1 = tf32r(v1);
                    *(float2*)(g_qkv_hi + off) = make_float2(h0, h1);
                    *(float2*)(g_qkv_lo + off) =
                        make_float2(tf32r(v0 - h0), tf32r(v1 - h1));
                } else {
                    *(float2*)(out + (size_t)m * NC + n) = make_float2(v0, v1);
                }
            }
        }
    }
}

// ---------------------------------------------------------------------------
// Attention: one CTA per (b,h). Pre-split tf32 hi/lo inputs; inner loops are
// pure LDS + mma (no cvt). Writes tf32-rounded fp32 to g_att.
// ---------------------------------------------------------------------------
struct AttnSmem {
    float Qh[64][36], Ql[64][36];
    float Kh[64][36], Kl[64][36];
    float Vh[64][36], Vl[64][36];
    float Ss[64][68];   // scores, then P_hi
    float Pl[64][68];   // P_lo
};

__global__ void __launch_bounds__(256) attn_kernel() {
    extern __shared__ char asm_raw[];
    AttnSmem& S = *reinterpret_cast<AttnSmem*>(asm_raw);

    const int bh  = blockIdx.x;
    const int h   = bh % NH;
    const int tid = threadIdx.x;

    const float* Qhg = g_qkv_hi + (size_t)bh * NT * ND;
    const float* Qlg = g_qkv_lo + (size_t)bh * NT * ND;
    const float* Khg = g_qkv_hi + SQ + (size_t)bh * NT * ND;
    const float* Klg = g_qkv_lo + SQ + (size_t)bh * NT * ND;
    const float* Vhg = g_qkv_hi + 2 * SQ + (size_t)bh * NT * ND;
    const float* Vlg = g_qkv_lo + 2 * SQ + (size_t)bh * NT * ND;

#pragma unroll
    for (int e = tid * 4; e < NT * ND; e += 1024) {
        const int t = e >> 5;
        const int d = e & 31;
        *(float4*)&S.Qh[t][d] = *(const float4*)(Qhg + e);
        *(float4*)&S.Ql[t][d] = *(const float4*)(Qlg + e);
        *(float4*)&S.Kh[t][d] = *(const float4*)(Khg + e);
        *(float4*)&S.Kl[t][d] = *(const float4*)(Klg + e);
        *(float4*)&S.Vh[t][d] = *(const float4*)(Vhg + e);
        *(float4*)&S.Vl[t][d] = *(const float4*)(Vlg + e);
    }
    __syncthreads();

    const int lane = tid & 31;
    const int warp = tid >> 5;
    const int rA = lane >> 2;
    const int cA = lane & 3;
    const int wm = (warp >> 1) * 16;
    const int wn = (warp & 1) * 32;

    // S = Q K^T  (3-term tf32, no cvt)
    float sc_[4][4];
#pragma unroll
    for (int i = 0; i < 4; i++)
#pragma unroll
        for (int r = 0; r < 4; r++) sc_[i][r] = 0.0f;

#pragma unroll
    for (int k0 = 0; k0 < 32; k0 += 8) {
        uint32_t ah[4], al[4];
        ah[0] = __float_as_uint(S.Qh[wm + rA][k0 + cA]);
        ah[1] = __float_as_uint(S.Qh[wm + 8 + rA][k0 + cA]);
        ah[2] = __float_as_uint(S.Qh[wm + rA][k0 + 4 + cA]);
        ah[3] = __float_as_uint(S.Qh[wm + 8 + rA][k0 + 4 + cA]);
        al[0] = __float_as_uint(S.Ql[wm + rA][k0 + cA]);
        al[1] = __float_as_uint(S.Ql[wm + 8 + rA][k0 + cA]);
        al[2] = __float_as_uint(S.Ql[wm + rA][k0 + 4 + cA]);
        al[3] = __float_as_uint(S.Ql[wm + 8 + rA][k0 + 4 + cA]);
#pragma unroll
        for (int tn = 0; tn < 4; tn++) {
            const int kr = wn + tn * 8 + rA;
            uint32_t bh0 = __float_as_uint(S.Kh[kr][k0 + cA]);
            uint32_t bh1 = __float_as_uint(S.Kh[kr][k0 + 4 + cA]);
            uint32_t bl0 = __float_as_uint(S.Kl[kr][k0 + cA]);
            uint32_t bl1 = __float_as_uint(S.Kl[kr][k0 + 4 + cA]);
            mma_tf32(sc_[tn], ah[0], ah[1], ah[2], ah[3], bh0, bh1);
            mma_tf32(sc_[tn], ah[0], ah[1], ah[2], ah[3], bl0, bl1);
            mma_tf32(sc_[tn], al[0], al[1], al[2], al[3], bh0, bh1);
        }
    }

    const float* bp = g_bias + h * NT * NT;
#pragma unroll
    for (int tn = 0; tn < 4; tn++) {
#pragma unroll
        for (int half = 0; half < 2; half++) {
            const int m = wm + rA + half * 8;
            const int n = wn + tn * 8 + cA * 2;
            float2 bz = *(const float2*)(bp + m * NT + n);
            *(float2*)&S.Ss[m][n] = make_float2(sc_[tn][half * 2 + 0] + bz.x,
                                                sc_[tn][half * 2 + 1] + bz.y);
        }
    }
    __syncthreads();

    // softmax: 8 warps x 8 rows; write P hi/lo planes
#pragma unroll
    for (int r = warp * 8; r < warp * 8 + 8; ++r) {
        float v0 = S.Ss[r][lane];
        float v1 = S.Ss[r][lane + 32];
        float mx = fmaxf(v0, v1);
#pragma unroll
        for (int o = 16; o; o >>= 1)
            mx = fmaxf(mx, __shfl_xor_sync(0xffffffffu, mx, o));
        float e0 = __expf(v0 - mx);
        float e1 = __expf(v1 - mx);
        float sm = e0 + e1;
#pragma unroll
        for (int o = 16; o; o >>= 1)
            sm += __shfl_xor_sync(0xffffffffu, sm, o);
        float inv = 1.0f / sm;
        float p0 = e0 * inv;
        float p1 = e1 * inv;
        float p0h = tf32r(p0), p1h = tf32r(p1);
        S.Ss[r][lane]      = p0h;
        S.Ss[r][lane + 32] = p1h;
        S.Pl[r][lane]      = tf32r(p0 - p0h);
        S.Pl[r][lane + 32] = tf32r(p1 - p1h);
    }
    __syncthreads();

    // O = P V  (3-term tf32, no cvt)
    const int wn2 = (warp & 1) * 16;
    float oc[2][4];
#pragma unroll
    for (int i = 0; i < 2; i++)
#pragma unroll
        for (int r = 0; r < 4; r++) oc[i][r] = 0.0f;

#pragma unroll
    for (int k0 = 0; k0 < 64; k0 += 8) {
        uint32_t ah[4], al[4];
        ah[0] = __float_as_uint(S.Ss[wm + rA][k0 + cA]);
        ah[1] = __float_as_uint(S.Ss[wm + 8 + rA][k0 + cA]);
        ah[2] = __float_as_uint(S.Ss[wm + rA][k0 + 4 + cA]);
        ah[3] = __float_as_uint(S.Ss[wm + 8 + rA][k0 + 4 + cA]);
        al[0] = __float_as_uint(S.Pl[wm + rA][k0 + cA]);
        al[1] = __float_as_uint(S.Pl[wm + 8 + rA][k0 + cA]);
        al[2] = __float_as_uint(S.Pl[wm + rA][k0 + 4 + cA]);
        al[3] = __float_as_uint(S.Pl[wm + 8 + rA][k0 + 4 + cA]);
#pragma unroll
        for (int tn = 0; tn < 2; tn++) {
            const int dc = wn2 + tn * 8 + rA;
            uint32_t bh0 = __float_as_uint(S.Vh[k0 + cA][dc]);
            uint32_t bh1 = __float_as_uint(S.Vh[k0 + 4 + cA][dc]);
            uint32_t bl0 = __float_as_uint(S.Vl[k0 + cA][dc]);
            uint32_t bl1 = __float_as_uint(S.Vl[k0 + 4 + cA][dc]);
            mma_tf32(oc[tn], ah[0], ah[1], ah[2], ah[3], bh0, bh1);
            mma_tf32(oc[tn], ah[0], ah[1], ah[2], ah[3], bl0, bl1);
            mma_tf32(oc[tn], al[0], al[1], al[2], al[3], bh0, bh1);
        }
    }

    const int b = bh / NH;
#pragma unroll
    for (int tn = 0; tn < 2; tn++) {
#pragma unroll
        for (int half = 0; half < 2; half++) {
            const int t = wm + rA + half * 8;
            const int d = wn2 + tn * 8 + cA * 2;
            float2 w2 = make_float2(tf32r(oc[tn][half * 2 + 0]),
                                    tf32r(oc[tn][half * 2 + 1]));
            *(float2*)&g_att[((size_t)(b * NT + t)) * NC + h * ND + d] = w2;
        }
    }
}

// ---------------------------------------------------------------------------
// Launch
// ---------------------------------------------------------------------------
extern "C" void kernel_launch(void* const* d_in, const int* in_sizes, int n_in,
                              void* d_out, int out_size) {
    const float* x      = (const float*)d_in[0];
    const float* qkv_w  = (const float*)d_in[1];
    const float* qkv_b  = (const float*)d_in[2];
    const float* proj_w = (const float*)d_in[3];
    const float* proj_b = (const float*)d_in[4];
    const float* rpb    = (const float*)d_in[5];
    const int*   rpi    = (const int*)d_in[6];
    float* out = (float*)d_out;

    cudaFuncSetAttribute(tf_gemm<0>, cudaFuncAttributeMaxDynamicSharedMemorySize, SMT);
    cudaFuncSetAttribute(tf_gemm<1>, cudaFuncAttributeMaxDynamicSharedMemorySize, SMT);
    cudaFuncSetAttribute(attn_kernel, cudaFuncAttributeMaxDynamicSharedMemorySize,
                         (int)sizeof(AttnSmem));

    float *xt, *qwt, *pwt, *att;
    cudaGetSymbolAddress((void**)&xt,  g_xt);
    cudaGetSymbolAddress((void**)&qwt, g_qwt);
    cudaGetSymbolAddress((void**)&pwt, g_pwt);
    cudaGetSymbolAddress((void**)&att, g_att);

    // tf32 pre-rounding
    {
        int n4 = (MT * NC) / 4;
        round_kernel<<<(n4 + 255) / 256, 256>>>(x, xt, n4);
        n4 = (N3C * NC) / 4;
        round_kernel<<<(n4 + 255) / 256, 256>>>(qkv_w, qwt, n4);
        n4 = (NC * NC) / 4;
        round_kernel<<<(n4 + 255) / 256, 256>>>(proj_w, pwt, n4);
    }
    bias_kernel<<<(NH * NT * NT + 255) / 256, 256>>>(rpb, rpi);

    dim3 g1(N3C / 128, MT / 256);   // (9, 512)
    tf_gemm<0><<<g1, 256, SMT>>>(xt, qwt, qkv_b, nullptr);

    attn_kernel<<<NB * NH, 256, sizeof(AttnSmem)>>>();

    dim3 g2(NC / 128, MT / 256);    // (3, 512)
    tf_gemm<1><<<g2, 256, SMT>>>(att, pwt, proj_b, out);
}

// round 8
// speedup vs baseline: 1.4307x; 1.4307x over previous
#include <cuda_runtime.h>
#include <cstdint>

// Problem constants
#define NB 2048
#define NT 64
#define NC 384
#define NH 12
#define ND 32
#define N3C 1152
#define MT 131072            // NB*NT rows
#define KDIM 384
#define SQ 50331648ull       // NB*NH*NT*ND

// ---------------- device scratch (no allocation allowed) -------------------
__device__ float g_qkv[3 * SQ];                     // (3,B,H,T,D) fp32
__device__ float g_bias[NH * NT * NT];              // (H,T,T)
__device__ float g_xt[(size_t)MT * NC];             // tf32-rounded x
__device__ float g_qwt[(size_t)N3C * NC];           // tf32-rounded qkv_w
__device__ float g_pwt[(size_t)NC * NC];            // tf32-rounded proj_w
__device__ float g_att[(size_t)MT * NC];            // attn output (tf32-rounded)

// ---------------- helpers ---------------------------------------------------
__device__ __forceinline__ uint32_t smem_u32(const void* p) {
    uint32_t a;
    asm("{ .reg .u64 t; cvta.to.shared.u64 t, %1; cvt.u32.u64 %0, t; }"
        : "=r"(a) : "l"(p));
    return a;
}
__device__ __forceinline__ float tf32r(float x) {
    uint32_t u; asm("cvt.rna.tf32.f32 %0, %1;" : "=r"(u) : "f"(x));
    return __uint_as_float(u);
}

#define CP_ASYNC16(dst, src) \
    asm volatile("cp.async.cg.shared.global [%0], [%1], 16;" \
                 :: "r"(dst), "l"(src) : "memory")
#define CP_COMMIT() asm volatile("cp.async.commit_group;" ::: "memory")
#define CP_WAIT(n)  asm volatile("cp.async.wait_group %0;" :: "n"(n) : "memory")

__device__ __forceinline__ void ldsm4(uint32_t& r0, uint32_t& r1,
                                      uint32_t& r2, uint32_t& r3, uint32_t a) {
    asm volatile("ldmatrix.sync.aligned.m8n8.x4.shared.b16 {%0,%1,%2,%3}, [%4];"
                 : "=r"(r0), "=r"(r1), "=r"(r2), "=r"(r3) : "r"(a));
}

__device__ __forceinline__ void mma_tf32(float c[4],
                                         uint32_t a0, uint32_t a1, uint32_t a2, uint32_t a3,
                                         uint32_t b0, uint32_t b1) {
    asm volatile(
        "mma.sync.aligned.m16n8k8.row.col.f32.tf32.tf32.f32 "
        "{%0,%1,%2,%3},{%4,%5,%6,%7},{%8,%9},{%0,%1,%2,%3};"
        : "+f"(c[0]), "+f"(c[1]), "+f"(c[2]), "+f"(c[3])
        : "r"(a0), "r"(a1), "r"(a2), "r"(a3), "r"(b0), "r"(b1));
}

// ---------------------------------------------------------------------------
// tf32 rounding pass (fp32 -> tf32-rounded fp32)
// ---------------------------------------------------------------------------
__global__ void round_kernel(const float* __restrict__ src,
                             float* __restrict__ dst, int n4) {
    int i = blockIdx.x * 256 + threadIdx.x;
    if (i >= n4) return;
    float4 v = ((const float4*)src)[i];
    v.x = tf32r(v.x); v.y = tf32r(v.y); v.z = tf32r(v.z); v.w = tf32r(v.w);
    ((float4*)dst)[i] = v;
}

// ---------------------------------------------------------------------------
// Bias gather
// ---------------------------------------------------------------------------
__global__ void bias_kernel(const float* __restrict__ rpb,
                            const int* __restrict__ rpi) {
    int i = blockIdx.x * 256 + threadIdx.x;
    if (i >= NH * NT * NT) return;
    int h  = i / (NT * NT);
    int qk = i - h * (NT * NT);
    g_bias[i] = rpb[rpi[qk] * NH + h];
}

// ---------------------------------------------------------------------------
// Single-pass TF32 GEMM: C[m][n] = sum_k A[m][k]*W[n][k] + bias[n]
// BM=BN=128, BK=32 fp32 (128B swizzled rows). 8 warps (2x4), warp tile 64x32.
// ldmatrix-b16 trick on fp32 quadrants. 3-stage cp.async pipeline,
// ONE __syncthreads per iteration.
// EPI==0: scatter into g_qkv with q-scale. EPI==1: write out (+bias).
// ---------------------------------------------------------------------------
#define STG 32768                // A 16KB + W 16KB per stage
#define SMT (3 * STG)            // 96 KB (3 stages)

template <int EPI>
__global__ void __launch_bounds__(256, 2)
tf_gemm(const float* __restrict__ A, const float* __restrict__ W,
        const float* __restrict__ bias, float* __restrict__ out) {
    extern __shared__ char smem[];
    const uint32_t sb = smem_u32(smem);

    const int tid  = threadIdx.x;
    const int warp = tid >> 5;
    const int lane = tid & 31;
    const int m0 = blockIdx.y * 128;
    const int n0 = blockIdx.x * 128;

    const int wm = (warp >> 2) * 64;    // 0 or 64
    const int wn = (warp & 3) * 32;     // 0,32,64,96

    // loaders: each thread cp.asyncs 4 chunks (16B) of A and of W per stage
    const int lrow = tid >> 1;
    const int lcb  = (tid & 1) * 4;
    const float* Ap = A + (size_t)(m0 + lrow) * KDIM + lcb * 4;
    const float* Wp = W + (size_t)(n0 + lrow) * KDIM + lcb * 4;
    const uint32_t lbase = lrow * 128;
    const int lsw = lrow & 7;

    auto fill = [&](int kc, int s) {
        const uint32_t base = sb + s * STG;
#pragma unroll
        for (int c = 0; c < 4; c++) {
            const uint32_t off = lbase + (((uint32_t)((lcb + c) ^ lsw)) << 4);
            CP_ASYNC16(base + off,         Ap + kc * 32 + c * 4);
            CP_ASYNC16(base + 16384 + off, Wp + kc * 32 + c * 4);
        }
    };

    float acc[4][4][4];
#pragma unroll
    for (int i = 0; i < 4; i++)
#pragma unroll
        for (int j = 0; j < 4; j++)
#pragma unroll
            for (int r = 0; r < 4; r++) acc[i][j][r] = 0.0f;

    const int mat = lane >> 3;      // 0..3
    const int mr  = lane & 7;       // 0..7

    fill(0, 0); CP_COMMIT();
    fill(1, 1); CP_COMMIT();

    int scur = 0;    // stage of kc
    int snxt = 2;    // stage of kc+2
    for (int kc = 0; kc < 12; ++kc) {
        if (kc + 2 < 12) { CP_WAIT(1); } else { CP_WAIT(0); }
        __syncthreads();                 // all warps done with compute(kc-1)
        if (kc + 2 < 12) {
            fill(kc + 2, snxt);          // overwrites stage read at kc-1: safe
            CP_COMMIT();
        }

        const uint32_t smA = sb + scur * STG;
        const uint32_t smW = smA + 16384;
        scur = (scur + 1 == 3) ? 0 : scur + 1;
        snxt = (snxt + 1 == 3) ? 0 : snxt + 1;

#pragma unroll
        for (int kg = 0; kg < 4; kg++) {   // 4 x k8 per BK=32
            uint32_t af[4][4];
            const uint32_t achunk = ((uint32_t)(kg * 2 + (mat >> 1)) ^ (uint32_t)mr) << 4;
            const uint32_t arow   = wm + ((mat & 1) << 3) + mr;
#pragma unroll
            for (int tm = 0; tm < 4; tm++) {
                const uint32_t ad = smA + (arow + tm * 16) * 128 + achunk;
                ldsm4(af[tm][0], af[tm][1], af[tm][2], af[tm][3], ad);
            }
            uint32_t bf[4][2];
            const uint32_t bchunk = ((uint32_t)(kg * 2 + (mat & 1)) ^ (uint32_t)mr) << 4;
#pragma unroll
            for (int p = 0; p < 2; p++) {
                const uint32_t brow = wn + (2 * p + (mat >> 1)) * 8 + mr;
                const uint32_t bd = smW + brow * 128 + bchunk;
                uint32_t t0, t1, t2, t3;
                ldsm4(t0, t1, t2, t3, bd);
                bf[2 * p][0] = t0; bf[2 * p][1] = t1;
                bf[2 * p + 1][0] = t2; bf[2 * p + 1][1] = t3;
            }
#pragma unroll
            for (int tm = 0; tm < 4; tm++)
#pragma unroll
                for (int tn = 0; tn < 4; tn++)
                    mma_tf32(acc[tm][tn], af[tm][0], af[tm][1], af[tm][2], af[tm][3],
                             bf[tn][0], bf[tn][1]);
        }
    }

    // epilogue: thread holds (rA, 2cA),(rA,2cA+1),(rA+8,..)
    const int rA = lane >> 2;
    const int cA = lane & 3;
#pragma unroll
    for (int tm = 0; tm < 4; tm++) {
#pragma unroll
        for (int tn = 0; tn < 4; tn++) {
#pragma unroll
            for (int half = 0; half < 2; half++) {
                const int m = m0 + wm + tm * 16 + rA + half * 8;
                const int n = n0 + wn + tn * 8 + cA * 2;
                float v0 = acc[tm][tn][half * 2 + 0] + bias[n];
                float v1 = acc[tm][tn][half * 2 + 1] + bias[n + 1];
                if (EPI == 0) {
                    const int s   = n / NC;
                    const int rem = n - s * NC;
                    const int h   = rem >> 5;
                    const int d0  = rem & 31;
                    if (s == 0) {
                        const float sc = 0.17677669529663687f;  // 1/sqrt(32)
                        v0 *= sc; v1 *= sc;
                    }
                    const int b = m >> 6;
                    const int t = m & 63;
                    float* dst = g_qkv + (size_t)s * SQ +
                                 (((size_t)(b * NH + h)) * NT + t) * ND + d0;
                    *(float2*)dst = make_float2(v0, v1);
                } else {
                    *(float2*)(out + (size_t)m * NC + n) = make_float2(v0, v1);
                }
            }
        }
    }
}

// ---------------------------------------------------------------------------
// Attention: one CTA per (b,h). 3xTF32 for QK^T and PV.
// Writes tf32-rounded fp32 to g_att (ready for the single-pass proj GEMM).
// ---------------------------------------------------------------------------
__global__ void __launch_bounds__(256) attn_kernel() {
    __shared__ float Qs[64][36];
    __shared__ float Ks[64][36];
    __shared__ float Vs[64][36];
    __shared__ float Ss[64][68];

    const int bh  = blockIdx.x;
    const int h   = bh % NH;
    const int tid = threadIdx.x;

    const float* Qg = g_qkv + (size_t)bh * NT * ND;
    const float* Kg = g_qkv + SQ + (size_t)bh * NT * ND;
    const float* Vg = g_qkv + 2 * SQ + (size_t)bh * NT * ND;

#pragma unroll
    for (int e = tid * 4; e < NT * ND; e += 1024) {
        const int t = e >> 5;
        const int d = e & 31;
        *(float4*)&Qs[t][d] = *(const float4*)(Qg + e);
        *(float4*)&Ks[t][d] = *(const float4*)(Kg + e);
        *(float4*)&Vs[t][d] = *(const float4*)(Vg + e);
    }
    __syncthreads();

    const int lane = tid & 31;
    const int warp = tid >> 5;
    const int rA = lane >> 2;
    const int cA = lane & 3;
    const int wm = (warp >> 1) * 16;
    const int wn = (warp & 1) * 32;

    // S = Q K^T (3xTF32)
    float sc_[4][4];
#pragma unroll
    for (int i = 0; i < 4; i++)
#pragma unroll
        for (int r = 0; r < 4; r++) sc_[i][r] = 0.0f;

#pragma unroll
    for (int k0 = 0; k0 < 32; k0 += 8) {
        float a[4];
        a[0] = Qs[wm + rA][k0 + cA];
        a[1] = Qs[wm + 8 + rA][k0 + cA];
        a[2] = Qs[wm + rA][k0 + 4 + cA];
        a[3] = Qs[wm + 8 + rA][k0 + 4 + cA];
        uint32_t ah[4], al[4];
#pragma unroll
        for (int i = 0; i < 4; i++) {
            float hv = tf32r(a[i]);
            ah[i] = __float_as_uint(hv);
            al[i] = __float_as_uint(tf32r(a[i] - hv));
        }
#pragma unroll
        for (int tn = 0; tn < 4; tn++) {
            float b0 = Ks[wn + tn * 8 + rA][k0 + cA];
            float b1 = Ks[wn + tn * 8 + rA][k0 + 4 + cA];
            float bh0 = tf32r(b0), bh1 = tf32r(b1);
            uint32_t ubh0 = __float_as_uint(bh0), ubh1 = __float_as_uint(bh1);
            uint32_t ubl0 = __float_as_uint(tf32r(b0 - bh0));
            uint32_t ubl1 = __float_as_uint(tf32r(b1 - bh1));
            mma_tf32(sc_[tn], ah[0], ah[1], ah[2], ah[3], ubh0, ubh1);
            mma_tf32(sc_[tn], ah[0], ah[1], ah[2], ah[3], ubl0, ubl1);
            mma_tf32(sc_[tn], al[0], al[1], al[2], al[3], ubh0, ubh1);
        }
    }

    const float* bp = g_bias + h * NT * NT;
#pragma unroll
    for (int tn = 0; tn < 4; tn++) {
#pragma unroll
        for (int half = 0; half < 2; half++) {
            const int m = wm + rA + half * 8;
            const int n = wn + tn * 8 + cA * 2;
            float2 bz = *(const float2*)(bp + m * NT + n);
            *(float2*)&Ss[m][n] = make_float2(sc_[tn][half * 2 + 0] + bz.x,
                                              sc_[tn][half * 2 + 1] + bz.y);
        }
    }
    __syncthreads();

    // softmax: 8 warps x 8 rows
#pragma unroll
    for (int r = warp * 8; r < warp * 8 + 8; ++r) {
        float v0 = Ss[r][lane];
        float v1 = Ss[r][lane + 32];
        float mx = fmaxf(v0, v1);
#pragma unroll
        for (int o = 16; o; o >>= 1)
            mx = fmaxf(mx, __shfl_xor_sync(0xffffffffu, mx, o));
        float e0 = __expf(v0 - mx);
        float e1 = __expf(v1 - mx);
        float sm = e0 + e1;
#pragma unroll
        for (int o = 16; o; o >>= 1)
            sm += __shfl_xor_sync(0xffffffffu, sm, o);
        float inv = 1.0f / sm;
        Ss[r][lane]      = e0 * inv;
        Ss[r][lane + 32] = e1 * inv;
    }
    __syncthreads();

    // O = P V (3xTF32)
    const int wn2 = (warp & 1) * 16;
    float oc[2][4];
#pragma unroll
    for (int i = 0; i < 2; i++)
#pragma unroll
        for (int r = 0; r < 4; r++) oc[i][r] = 0.0f;

#pragma unroll
    for (int k0 = 0; k0 < 64; k0 += 8) {
        float a[4];
        a[0] = Ss[wm + rA][k0 + cA];
        a[1] = Ss[wm + 8 + rA][k0 + cA];
        a[2] = Ss[wm + rA][k0 + 4 + cA];
        a[3] = Ss[wm + 8 + rA][k0 + 4 + cA];
        uint32_t ah[4], al[4];
#pragma unroll
        for (int i = 0; i < 4; i++) {
            float hv = tf32r(a[i]);
            ah[i] = __float_as_uint(hv);
            al[i] = __float_as_uint(tf32r(a[i] - hv));
        }
#pragma unroll
        for (int tn = 0; tn < 2; tn++) {
            float b0 = Vs[k0 + cA][wn2 + tn * 8 + rA];
            float b1 = Vs[k0 + 4 + cA][wn2 + tn * 8 + rA];
            float bh0 = tf32r(b0), bh1 = tf32r(b1);
            uint32_t ubh0 = __float_as_uint(bh0), ubh1 = __float_as_uint(bh1);
            uint32_t ubl0 = __float_as_uint(tf32r(b0 - bh0));
            uint32_t ubl1 = __float_as_uint(tf32r(b1 - bh1));
            mma_tf32(oc[tn], ah[0], ah[1], ah[2], ah[3], ubh0, ubh1);
            mma_tf32(oc[tn], ah[0], ah[1], ah[2], ah[3], ubl0, ubl1);
            mma_tf32(oc[tn], al[0], al[1], al[2], al[3], ubh0, ubh1);
        }
    }

    const int b = bh / NH;
#pragma unroll
    for (int tn = 0; tn < 2; tn++) {
#pragma unroll
        for (int half = 0; half < 2; half++) {
            const int t = wm + rA + half * 8;
            const int d = wn2 + tn * 8 + cA * 2;
            // tf32-round so the proj GEMM can run single-pass
            float2 w2 = make_float2(tf32r(oc[tn][half * 2 + 0]),
                                    tf32r(oc[tn][half * 2 + 1]));
            *(float2*)&g_att[((size_t)(b * NT + t)) * NC + h * ND + d] = w2;
        }
    }
}

// ---------------------------------------------------------------------------
// Launch  (order arranged so launch #4 = tf_gemm<0> for ncu capture)
// ---------------------------------------------------------------------------
extern "C" void kernel_launch(void* const* d_in, const int* in_sizes, int n_in,
                              void* d_out, int out_size) {
    const float* x      = (const float*)d_in[0];
    const float* qkv_w  = (const float*)d_in[1];
    const float* qkv_b  = (const float*)d_in[2];
    const float* proj_w = (const float*)d_in[3];
    const float* proj_b = (const float*)d_in[4];
    const float* rpb    = (const float*)d_in[5];
    const int*   rpi    = (const int*)d_in[6];
    float* out = (float*)d_out;

    cudaFuncSetAttribute(tf_gemm<0>, cudaFuncAttributeMaxDynamicSharedMemorySize, SMT);
    cudaFuncSetAttribute(tf_gemm<1>, cudaFuncAttributeMaxDynamicSharedMemorySize, SMT);

    float *xt, *qwt, *pwt, *att;
    cudaGetSymbolAddress((void**)&xt,  g_xt);
    cudaGetSymbolAddress((void**)&qwt, g_qwt);
    cudaGetSymbolAddress((void**)&pwt, g_pwt);
    cudaGetSymbolAddress((void**)&att, g_att);

    // tf32 pre-rounding (launches 1-3)
    {
        int n4 = (MT * NC) / 4;
        round_kernel<<<(n4 + 255) / 256, 256>>>(x, xt, n4);
        n4 = (N3C * NC) / 4;
        round_kernel<<<(n4 + 255) / 256, 256>>>(qkv_w, qwt, n4);
        n4 = (NC * NC) / 4;
        round_kernel<<<(n4 + 255) / 256, 256>>>(proj_w, pwt, n4);
    }

    // launch 4: the big QKV GEMM (profiled slot)
    dim3 g1(N3C / 128, MT / 128);   // (9, 1024)
    tf_gemm<0><<<g1, 256, SMT>>>(xt, qwt, qkv_b, nullptr);

    // launch 5: bias gather (only needed before attn)
    bias_kernel<<<(NH * NT * NT + 255) / 256, 256>>>(rpb, rpi);

    // launch 6: attention
    attn_kernel<<<NB * NH, 256>>>();

    // launch 7: projection GEMM
    dim3 g2(NC / 128, MT / 128);    // (3, 1024)
    tf_gemm<1><<<g2, 256, SMT>>>(att, pwt, proj_b, out);
}